// round 4
// baseline (speedup 1.0000x reference)
#include <cuda_runtime.h>
#include <cuda_bf16.h>
#include <math.h>

// Problem dims (fixed)
#define BB 2
#define QQ 2048
#define CQd 512
#define NH 8
#define HD 64
#define MROWS (BB * QQ)   // 4096
#define NCOLS 2048        // 3*H*D (qkv) + H*D (gate)
#define KDIM 512

// Scratch (no allocations allowed -> device globals)
__device__ float g_qkvg[(size_t)MROWS * NCOLS]; // [4096][2048]: q(0..511 scaled)|k|v|sigmoid(gate)
__device__ float g_o[(size_t)MROWS * 512];      // gated attention output

// ---------------------------------------------------------------------------
// Kernel 1: fused QKV + gate projection
// C[m][n] = sum_c A[m][c] * W[n][c];  W rows 0..1535 = w_qkv, 1536..2047 = w_g
// epilogue: n<512 -> *1/8 ;  n>=1536 -> sigmoid(x + b_g)
// 128x128x16 tiles, 256 threads, 8x8 microtile, register prefetch
// ---------------------------------------------------------------------------
__global__ __launch_bounds__(256) void k_gemm_qkvg(
    const float* __restrict__ A,
    const float* __restrict__ Wqkv,
    const float* __restrict__ Wg,
    const float* __restrict__ bg)
{
    __shared__ float As[16 * 132];
    __shared__ float Bs[16 * 132];
    const int tid = threadIdx.x;
    const int tx = tid & 15;
    const int ty = tid >> 4;
    const int m0 = blockIdx.y * 128;
    const int n0 = blockIdx.x * 128;

    const float* Asrc = A + (size_t)m0 * KDIM;
    const float* Bsrc = (n0 < 1536) ? (Wqkv + (size_t)n0 * KDIM)
                                    : (Wg + (size_t)(n0 - 1536) * KDIM);

    const int lr0 = tid >> 2;        // 0..63
    const int lk  = (tid & 3) << 2;  // 0,4,8,12

    float acc[8][8];
#pragma unroll
    for (int i = 0; i < 8; ++i)
#pragma unroll
        for (int j = 0; j < 8; ++j) acc[i][j] = 0.f;

    float4 a0 = *(const float4*)(Asrc + (size_t)lr0 * KDIM + lk);
    float4 a1 = *(const float4*)(Asrc + (size_t)(lr0 + 64) * KDIM + lk);
    float4 b0 = *(const float4*)(Bsrc + (size_t)lr0 * KDIM + lk);
    float4 b1 = *(const float4*)(Bsrc + (size_t)(lr0 + 64) * KDIM + lk);

    for (int kt = 0; kt < KDIM / 16; ++kt) {
        As[(lk + 0) * 132 + lr0] = a0.x;
        As[(lk + 1) * 132 + lr0] = a0.y;
        As[(lk + 2) * 132 + lr0] = a0.z;
        As[(lk + 3) * 132 + lr0] = a0.w;
        As[(lk + 0) * 132 + lr0 + 64] = a1.x;
        As[(lk + 1) * 132 + lr0 + 64] = a1.y;
        As[(lk + 2) * 132 + lr0 + 64] = a1.z;
        As[(lk + 3) * 132 + lr0 + 64] = a1.w;
        Bs[(lk + 0) * 132 + lr0] = b0.x;
        Bs[(lk + 1) * 132 + lr0] = b0.y;
        Bs[(lk + 2) * 132 + lr0] = b0.z;
        Bs[(lk + 3) * 132 + lr0] = b0.w;
        Bs[(lk + 0) * 132 + lr0 + 64] = b1.x;
        Bs[(lk + 1) * 132 + lr0 + 64] = b1.y;
        Bs[(lk + 2) * 132 + lr0 + 64] = b1.z;
        Bs[(lk + 3) * 132 + lr0 + 64] = b1.w;
        __syncthreads();

        if (kt < KDIM / 16 - 1) {
            const int kc = (kt + 1) * 16 + lk;
            a0 = *(const float4*)(Asrc + (size_t)lr0 * KDIM + kc);
            a1 = *(const float4*)(Asrc + (size_t)(lr0 + 64) * KDIM + kc);
            b0 = *(const float4*)(Bsrc + (size_t)lr0 * KDIM + kc);
            b1 = *(const float4*)(Bsrc + (size_t)(lr0 + 64) * KDIM + kc);
        }

#pragma unroll
        for (int k = 0; k < 16; ++k) {
            float4 ra0 = *(const float4*)(&As[k * 132 + ty * 4]);
            float4 ra1 = *(const float4*)(&As[k * 132 + 64 + ty * 4]);
            float4 rb0 = *(const float4*)(&Bs[k * 132 + tx * 4]);
            float4 rb1 = *(const float4*)(&Bs[k * 132 + 64 + tx * 4]);
            float af[8] = {ra0.x, ra0.y, ra0.z, ra0.w, ra1.x, ra1.y, ra1.z, ra1.w};
            float bf[8] = {rb0.x, rb0.y, rb0.z, rb0.w, rb1.x, rb1.y, rb1.z, rb1.w};
#pragma unroll
            for (int i = 0; i < 8; ++i)
#pragma unroll
                for (int j = 0; j < 8; ++j)
                    acc[i][j] = fmaf(af[i], bf[j], acc[i][j]);
        }
        __syncthreads();
    }

    const float qscale = (n0 < 512) ? 0.125f : 1.0f;  // 1/sqrt(64)
    const bool gatep = (n0 >= 1536);
#pragma unroll
    for (int i = 0; i < 8; ++i) {
        const int m = m0 + ((i < 4) ? (ty * 4 + i) : (64 + ty * 4 + (i - 4)));
#pragma unroll
        for (int jh = 0; jh < 2; ++jh) {
            const int n = n0 + jh * 64 + tx * 4;
            float v[4];
#pragma unroll
            for (int c = 0; c < 4; ++c) v[c] = acc[i][jh * 4 + c] * qscale;
            if (gatep) {
#pragma unroll
                for (int c = 0; c < 4; ++c) {
                    const float x = v[c] + bg[n - 1536 + c];
                    v[c] = 1.0f / (1.0f + __expf(-x));
                }
            }
            float4 o4 = make_float4(v[0], v[1], v[2], v[3]);
            *(float4*)(&g_qkvg[(size_t)m * NCOLS + n]) = o4;
        }
    }
}

// ---------------------------------------------------------------------------
// Kernel 2: flash attention with additive bias + fused sigmoid gate
// block = (q-tile 64, head, batch); 256 threads; 4x4 microtiles
// ---------------------------------------------------------------------------
#define QT 64
#define PAD 68
#define FLASH_SMEM (3 * 64 * PAD * sizeof(float))

__global__ __launch_bounds__(256) void k_flash(const float* __restrict__ bias)
{
    extern __shared__ float sm[];
    float* Qt  = sm;                  // [d][r], stride PAD (d-major)
    float* KtP = sm + 64 * PAD;       // Kt [d][c]; reused as Pt [c][r]
    float* Vs  = sm + 2 * 64 * PAD;   // [j][dv]

    const int tid = threadIdx.x;
    const int tx = tid & 15;
    const int ty = tid >> 4;
    const int q0 = blockIdx.x * QT;
    const int h  = blockIdx.y;
    const int b  = blockIdx.z;

    const size_t rbase = (size_t)b * QQ;
    const float* biasb = bias + (size_t)b * QQ * QQ;
    const int hq = h * HD;

    // Load Q tile transposed (already scaled by 1/8 in kernel 1)
#pragma unroll
    for (int it = 0; it < 4; ++it) {
        const int a = tid + it * 256;
        const int r = a >> 4;
        const int d0 = (a & 15) << 2;
        float4 v = *(const float4*)(&g_qkvg[(rbase + q0 + r) * NCOLS + hq + d0]);
        Qt[(d0 + 0) * PAD + r] = v.x;
        Qt[(d0 + 1) * PAD + r] = v.y;
        Qt[(d0 + 2) * PAD + r] = v.z;
        Qt[(d0 + 3) * PAD + r] = v.w;
    }

    float mrow[4], lrow[4], acc[4][4];
#pragma unroll
    for (int i = 0; i < 4; ++i) {
        mrow[i] = -3.0e38f;
        lrow[i] = 0.f;
#pragma unroll
        for (int j = 0; j < 4; ++j) acc[i][j] = 0.f;
    }

    for (int kt = 0; kt < QQ / QT; ++kt) {
        const int k0 = kt * QT;
        __syncthreads();  // previous iter's Pt/Vs reads complete before overwrite
        // Load K tile (transposed) and V tile (natural)
#pragma unroll
        for (int it = 0; it < 4; ++it) {
            const int a = tid + it * 256;
            const int r = a >> 4;
            const int d0 = (a & 15) << 2;
            const float* src = &g_qkvg[(rbase + k0 + r) * NCOLS];
            float4 kv = *(const float4*)(src + 512 + hq + d0);
            KtP[(d0 + 0) * PAD + r] = kv.x;
            KtP[(d0 + 1) * PAD + r] = kv.y;
            KtP[(d0 + 2) * PAD + r] = kv.z;
            KtP[(d0 + 3) * PAD + r] = kv.w;
            *(float4*)(&Vs[r * PAD + d0]) = *(const float4*)(src + 1024 + hq + d0);
        }
        __syncthreads();

        // S = Q K^T  (4x4 microtile per thread)
        float s[4][4];
#pragma unroll
        for (int i = 0; i < 4; ++i)
#pragma unroll
            for (int j = 0; j < 4; ++j) s[i][j] = 0.f;
#pragma unroll 8
        for (int d = 0; d < 64; ++d) {
            float4 qa = *(const float4*)(&Qt[d * PAD + ty * 4]);
            float4 kb = *(const float4*)(&KtP[d * PAD + tx * 4]);
            float af[4] = {qa.x, qa.y, qa.z, qa.w};
            float bf[4] = {kb.x, kb.y, kb.z, kb.w};
#pragma unroll
            for (int i = 0; i < 4; ++i)
#pragma unroll
                for (int j = 0; j < 4; ++j)
                    s[i][j] = fmaf(af[i], bf[j], s[i][j]);
        }
        // additive pairwise bias
#pragma unroll
        for (int i = 0; i < 4; ++i) {
            float4 bb = *(const float4*)(biasb + (size_t)(q0 + ty * 4 + i) * QQ + k0 + tx * 4);
            s[i][0] += bb.x; s[i][1] += bb.y; s[i][2] += bb.z; s[i][3] += bb.w;
        }
        // online softmax (row group = 16 consecutive lanes = half warp)
#pragma unroll
        for (int i = 0; i < 4; ++i) {
            float mx = fmaxf(fmaxf(s[i][0], s[i][1]), fmaxf(s[i][2], s[i][3]));
#pragma unroll
            for (int o = 8; o > 0; o >>= 1)
                mx = fmaxf(mx, __shfl_xor_sync(0xffffffffu, mx, o));
            const float mnew = fmaxf(mrow[i], mx);
            const float p0 = __expf(s[i][0] - mnew);
            const float p1 = __expf(s[i][1] - mnew);
            const float p2 = __expf(s[i][2] - mnew);
            const float p3 = __expf(s[i][3] - mnew);
            float rs = (p0 + p1) + (p2 + p3);
#pragma unroll
            for (int o = 8; o > 0; o >>= 1)
                rs += __shfl_xor_sync(0xffffffffu, rs, o);
            const float scale = __expf(mrow[i] - mnew);
            lrow[i] = lrow[i] * scale + rs;
            mrow[i] = mnew;
            acc[i][0] *= scale; acc[i][1] *= scale;
            acc[i][2] *= scale; acc[i][3] *= scale;
            s[i][0] = p0; s[i][1] = p1; s[i][2] = p2; s[i][3] = p3;
        }
        __syncthreads();  // all Kt reads done before Pt overwrite
        // write P transposed into the K buffer: Pt[c][r]
#pragma unroll
        for (int j = 0; j < 4; ++j)
#pragma unroll
            for (int i = 0; i < 4; ++i)
                KtP[(tx * 4 + j) * PAD + ty * 4 + i] = s[i][j];
        __syncthreads();
        // O += P V
#pragma unroll 8
        for (int j = 0; j < 64; ++j) {
            float4 pa = *(const float4*)(&KtP[j * PAD + ty * 4]);
            float4 vb = *(const float4*)(&Vs[j * PAD + tx * 4]);
            float af[4] = {pa.x, pa.y, pa.z, pa.w};
            float bf[4] = {vb.x, vb.y, vb.z, vb.w};
#pragma unroll
            for (int i = 0; i < 4; ++i)
#pragma unroll
                for (int jj = 0; jj < 4; ++jj)
                    acc[i][jj] = fmaf(af[i], bf[jj], acc[i][jj]);
        }
    }

    // epilogue: normalize + sigmoid gate, store to g_o
#pragma unroll
    for (int i = 0; i < 4; ++i) {
        const size_t row = rbase + q0 + ty * 4 + i;
        const float inv = 1.0f / lrow[i];
        float4 g4 = *(const float4*)(&g_qkvg[row * NCOLS + 1536 + hq + tx * 4]);
        float4 o4;
        o4.x = acc[i][0] * inv * g4.x;
        o4.y = acc[i][1] * inv * g4.y;
        o4.z = acc[i][2] * inv * g4.z;
        o4.w = acc[i][3] * inv * g4.w;
        *(float4*)(&g_o[row * 512 + hq + tx * 4]) = o4;
    }
}

// ---------------------------------------------------------------------------
// Kernel 3: output projection  out[m][n] = sum_e g_o[m][e]*w_o[n][e] + b_o[n]
// ---------------------------------------------------------------------------
__global__ __launch_bounds__(256) void k_gemm_out(
    const float* __restrict__ Wo,
    const float* __restrict__ bo,
    float* __restrict__ out)
{
    __shared__ float As[16 * 132];
    __shared__ float Bs[16 * 132];
    const int tid = threadIdx.x;
    const int tx = tid & 15;
    const int ty = tid >> 4;
    const int m0 = blockIdx.y * 128;
    const int n0 = blockIdx.x * 128;

    const float* Asrc = g_o + (size_t)m0 * KDIM;
    const float* Bsrc = Wo + (size_t)n0 * KDIM;

    const int lr0 = tid >> 2;
    const int lk  = (tid & 3) << 2;

    float acc[8][8];
#pragma unroll
    for (int i = 0; i < 8; ++i)
#pragma unroll
        for (int j = 0; j < 8; ++j) acc[i][j] = 0.f;

    float4 a0 = *(const float4*)(Asrc + (size_t)lr0 * KDIM + lk);
    float4 a1 = *(const float4*)(Asrc + (size_t)(lr0 + 64) * KDIM + lk);
    float4 b0 = *(const float4*)(Bsrc + (size_t)lr0 * KDIM + lk);
    float4 b1 = *(const float4*)(Bsrc + (size_t)(lr0 + 64) * KDIM + lk);

    for (int kt = 0; kt < KDIM / 16; ++kt) {
        As[(lk + 0) * 132 + lr0] = a0.x;
        As[(lk + 1) * 132 + lr0] = a0.y;
        As[(lk + 2) * 132 + lr0] = a0.z;
        As[(lk + 3) * 132 + lr0] = a0.w;
        As[(lk + 0) * 132 + lr0 + 64] = a1.x;
        As[(lk + 1) * 132 + lr0 + 64] = a1.y;
        As[(lk + 2) * 132 + lr0 + 64] = a1.z;
        As[(lk + 3) * 132 + lr0 + 64] = a1.w;
        Bs[(lk + 0) * 132 + lr0] = b0.x;
        Bs[(lk + 1) * 132 + lr0] = b0.y;
        Bs[(lk + 2) * 132 + lr0] = b0.z;
        Bs[(lk + 3) * 132 + lr0] = b0.w;
        Bs[(lk + 0) * 132 + lr0 + 64] = b1.x;
        Bs[(lk + 1) * 132 + lr0 + 64] = b1.y;
        Bs[(lk + 2) * 132 + lr0 + 64] = b1.z;
        Bs[(lk + 3) * 132 + lr0 + 64] = b1.w;
        __syncthreads();

        if (kt < KDIM / 16 - 1) {
            const int kc = (kt + 1) * 16 + lk;
            a0 = *(const float4*)(Asrc + (size_t)lr0 * KDIM + kc);
            a1 = *(const float4*)(Asrc + (size_t)(lr0 + 64) * KDIM + kc);
            b0 = *(const float4*)(Bsrc + (size_t)lr0 * KDIM + kc);
            b1 = *(const float4*)(Bsrc + (size_t)(lr0 + 64) * KDIM + kc);
        }

#pragma unroll
        for (int k = 0; k < 16; ++k) {
            float4 ra0 = *(const float4*)(&As[k * 132 + ty * 4]);
            float4 ra1 = *(const float4*)(&As[k * 132 + 64 + ty * 4]);
            float4 rb0 = *(const float4*)(&Bs[k * 132 + tx * 4]);
            float4 rb1 = *(const float4*)(&Bs[k * 132 + 64 + tx * 4]);
            float af[8] = {ra0.x, ra0.y, ra0.z, ra0.w, ra1.x, ra1.y, ra1.z, ra1.w};
            float bf[8] = {rb0.x, rb0.y, rb0.z, rb0.w, rb1.x, rb1.y, rb1.z, rb1.w};
#pragma unroll
            for (int i = 0; i < 8; ++i)
#pragma unroll
                for (int j = 0; j < 8; ++j)
                    acc[i][j] = fmaf(af[i], bf[j], acc[i][j]);
        }
        __syncthreads();
    }

#pragma unroll
    for (int i = 0; i < 8; ++i) {
        const int m = m0 + ((i < 4) ? (ty * 4 + i) : (64 + ty * 4 + (i - 4)));
#pragma unroll
        for (int jh = 0; jh < 2; ++jh) {
            const int n = n0 + jh * 64 + tx * 4;
            float4 o4;
            o4.x = acc[i][jh * 4 + 0] + bo[n + 0];
            o4.y = acc[i][jh * 4 + 1] + bo[n + 1];
            o4.z = acc[i][jh * 4 + 2] + bo[n + 2];
            o4.w = acc[i][jh * 4 + 3] + bo[n + 3];
            *(float4*)(&out[(size_t)m * 512 + n]) = o4;
        }
    }
}

// ---------------------------------------------------------------------------
extern "C" void kernel_launch(void* const* d_in, const int* in_sizes, int n_in,
                              void* d_out, int out_size)
{
    (void)in_sizes; (void)n_in; (void)out_size;
    const float* q_x   = (const float*)d_in[0];
    // d_in[1] = kv_x (unused by the reference)
    const float* bias  = (const float*)d_in[2];
    const float* w_qkv = (const float*)d_in[3];
    const float* w_o   = (const float*)d_in[4];
    const float* b_o   = (const float*)d_in[5];
    const float* w_g   = (const float*)d_in[6];
    const float* b_g   = (const float*)d_in[7];
    float* out = (float*)d_out;

    // host-side attribute set: not a stream op, graph-capture safe
    cudaFuncSetAttribute(k_flash, cudaFuncAttributeMaxDynamicSharedMemorySize,
                         (int)FLASH_SMEM);

    dim3 g1(NCOLS / 128, MROWS / 128);  // (16, 32)
    k_gemm_qkvg<<<g1, 256>>>(q_x, w_qkv, w_g, b_g);

    dim3 g2(QQ / QT, NH, BB);           // (32, 8, 2)
    k_flash<<<g2, 256, FLASH_SMEM>>>(bias);

    dim3 g3(512 / 128, MROWS / 128);    // (4, 32)
    k_gemm_out<<<g3, 256>>>(w_o, b_o, out);
}